// round 8
// baseline (speedup 1.0000x reference)
#include <cuda_runtime.h>
#include <cuda_bf16.h>

#define HW   56
#define TS   59          // padded smem row stride (odd -> conflict-spread)
#define KSEL 30
#define NT   448         // threads: 448 * 7 = 3136, all active
#define NV   7           // pixels per thread
#define TMAX 448         // candidate capacity (bound: 7*30 = 210 + band margin)

__global__ __launch_bounds__(NT, 3)
void topk_spatial_kernel(const float* __restrict__ x,
                         const float* __restrict__ wgt,
                         const float* __restrict__ bias,
                         float* __restrict__ out,
                         int C)
{
    __shared__ float    tile[58 * TS];   // rows 0..57 (borders zero), stride TS
    __shared__ unsigned hist[2][256];    // double-buffered radix histograms
    __shared__ float    wsm[10];
    __shared__ unsigned sh_dsel, sh_krem;
    __shared__ float    xmax_sm[14];
    __shared__ int      tcnt;
    __shared__ unsigned keepbm[98];      // 3136-bit keep bitmap
    __shared__ double   csc[TMAX];       // candidate exact scores
    __shared__ int      cidx[TMAX];      // candidate flat indices

    const int tid = threadIdx.x;
    const int bc  = blockIdx.x;
    const int ch  = bc % C;
    const float* gx = x   + (size_t)bc * (HW * HW);
    float*       go = out + (size_t)bc * (HW * HW);

    if (tid < 9)  wsm[tid] = wgt[ch * 9 + tid];
    if (tid == 9) wsm[9]   = bias[ch];
    if (tid == 10) tcnt = 0;
    if (tid < 256) { hist[0][tid] = 0; hist[1][tid] = 0; }
    if (tid < 98)  keepbm[tid] = 0;

    // ---- zero borders of the 58x58 logical tile ----
    if (tid < 232) {
        int i = tid;
        if      (i < 58)  tile[i] = 0.f;
        else if (i < 116) tile[57 * TS + (i - 58)] = 0.f;
        else if (i < 174) tile[(i - 116) * TS] = 0.f;
        else              tile[(i - 174) * TS + 57] = 0.f;
    }

    // ---- load interior (float4), tracking max|x| for the error bound ----
    float maxv = 0.0f;
    const float4* gx4 = reinterpret_cast<const float4*>(gx);
    for (int i = tid; i < (HW * HW) / 4; i += NT) {
        float4 v = gx4[i];
        maxv = fmaxf(maxv, fmaxf(fmaxf(fabsf(v.x), fabsf(v.y)),
                                 fmaxf(fabsf(v.z), fabsf(v.w))));
        int p  = i * 4;
        int r  = p / HW;
        int cc = p - r * HW;
        float* t = &tile[(r + 1) * TS + cc + 1];
        t[0] = v.x; t[1] = v.y; t[2] = v.z; t[3] = v.w;
    }
    #pragma unroll
    for (int d = 16; d > 0; d >>= 1)
        maxv = fmaxf(maxv, __shfl_xor_sync(0xFFFFFFFFu, maxv, d));
    if ((tid & 31) == 0) xmax_sm[tid >> 5] = maxv;
    __syncthreads();

    const float w0 = wsm[0], w1 = wsm[1], w2 = wsm[2];
    const float w3 = wsm[3], w4 = wsm[4], w5 = wsm[5];
    const float w6 = wsm[6], w7 = wsm[7], w8 = wsm[8];
    const float bv = wsm[9];

    const int row  = tid >> 3;            // 0..55
    const int c0   = (tid & 7) * NV;      // 0,7,...,49
    const int lane = tid & 31;

    // ---- fp32 conv; scores kept as floats, per-thread max tracked ----
    float sc[NV];
    float smax = -3.4e38f;
    {
        const float* t0 = &tile[row * TS + c0];   // r-1 taps
        const float* t1 = t0 + TS;                // r   taps
        const float* t2 = t1 + TS;                // r+1 taps
        float a0 = t0[0], a1 = t0[1];
        float b0 = t1[0], b1 = t1[1];
        float d0 = t2[0], d1 = t2[1];
        #pragma unroll
        for (int j = 0; j < NV; ++j) {
            float a2 = t0[j + 2], b2 = t1[j + 2], d2 = t2[j + 2];
            float s = bv;
            s = fmaf(w0, a0, s); s = fmaf(w1, a1, s); s = fmaf(w2, a2, s);
            s = fmaf(w3, b0, s); s = fmaf(w4, b1, s); s = fmaf(w5, b2, s);
            s = fmaf(w6, d0, s); s = fmaf(w7, d1, s); s = fmaf(w8, d2, s);
            sc[j] = s;
            smax = fmaxf(smax, s);
            a0 = a1; a1 = a2; b0 = b1; b1 = b2; d0 = d1; d1 = d2;
        }
    }
    // map ONLY the per-thread max to an order-preserving uint key
    unsigned mu = __float_as_uint(smax);
    const unsigned maxkey = mu ^ ((unsigned)(((int)mu) >> 31) | 0x80000000u);

    // ---- radix select rank-KSEL among the 448 per-thread maxima.
    //      Lemma: maxima come from disjoint groups => >=KSEL elements >= M30. ----
    unsigned prefix = 0;
    unsigned krem   = KSEL;
    #pragma unroll
    for (int pass = 0; pass < 4; ++pass) {
        const int cur   = pass & 1;
        const int shift = 24 - 8 * pass;
        {
            unsigned v  = maxkey;
            bool ok = (((unsigned long long)v) >> (shift + 8)) ==
                      (unsigned long long)prefix;
            unsigned digit = ok ? ((v >> shift) & 255u) : 0xFFFFFFFFu;
            unsigned m = __match_any_sync(0xFFFFFFFFu, digit);
            if (ok && ((__ffs(m) - 1) == lane))
                atomicAdd(&hist[cur][digit], (unsigned)__popc(m));
            if (tid < 256) hist[cur ^ 1][tid] = 0;   // pre-zero next buffer
        }
        __syncthreads();

        if (tid < 32) {
            unsigned loc[8];
            unsigned run = 0;
            #pragma unroll
            for (int j = 7; j >= 0; --j) { run += hist[cur][lane * 8 + j]; loc[j] = run; }
            unsigned laneTotal = run;
            unsigned incl = laneTotal;
            #pragma unroll
            for (int d = 1; d < 32; d <<= 1) {
                unsigned t = __shfl_down_sync(0xFFFFFFFFu, incl, d);
                if (lane + d < 32) incl += t;
            }
            unsigned hiSum = incl - laneTotal;
            #pragma unroll
            for (int j = 0; j < 8; ++j) {
                unsigned suf  = hiSum + loc[j];                         // count >= bin
                unsigned sufn = (j < 7) ? (hiSum + loc[j + 1]) : hiSum; // count >  bin
                if (suf >= krem && sufn < krem) {
                    sh_dsel = (unsigned)(lane * 8 + j);
                    sh_krem = krem - sufn;
                }
            }
        }
        __syncthreads();
        prefix = (prefix << 8) | sh_dsel;
        krem   = sh_krem;
    }
    const unsigned M30key = prefix;

    // ---- guard-band threshold in FLOAT space: Tc = M30 - 2E ----
    float xmax = xmax_sm[0];
    #pragma unroll
    for (int i = 1; i < 14; ++i) xmax = fmaxf(xmax, xmax_sm[i]);
    const float wsum = fabsf(w0) + fabsf(w1) + fabsf(w2) + fabsf(w3) + fabsf(w4)
                     + fabsf(w5) + fabsf(w6) + fabsf(w7) + fabsf(w8);
    const float E = (wsum * xmax + fabsf(bv)) * 1.2e-6f;   // ~20 ulp bound, 2x margin

    unsigned tu = (M30key & 0x80000000u) ? (M30key ^ 0x80000000u) : ~M30key;
    const float Tc = __uint_as_float(tu) - 2.0f * E;

    // ---- Phase A: collect candidate indices (skip loop if thread max < Tc) ----
    if (smax >= Tc) {
        #pragma unroll
        for (int j = 0; j < NV; ++j) {
            if (sc[j] >= Tc) {
                int pos = atomicAdd(&tcnt, 1);
                if (pos < TMAX) cidx[pos] = row * HW + c0 + j;
            }
        }
    }
    __syncthreads();
    const int ntie = (tcnt < TMAX) ? tcnt : TMAX;

    // ---- Phase B: one thread per candidate computes the EXACT double score ----
    if (tid < ntie) {
        int p = cidx[tid];
        int r = p / HW, cc = p - r * HW;
        const float* t0 = &tile[r * TS + cc];     // top-left tap of this pixel
        double s = (double)bv;
        s = fma((double)w0, (double)t0[0],        s);
        s = fma((double)w1, (double)t0[1],        s);
        s = fma((double)w2, (double)t0[2],        s);
        s = fma((double)w3, (double)t0[TS],       s);
        s = fma((double)w4, (double)t0[TS + 1],   s);
        s = fma((double)w5, (double)t0[TS + 2],   s);
        s = fma((double)w6, (double)t0[2*TS],     s);
        s = fma((double)w7, (double)t0[2*TS + 1], s);
        s = fma((double)w8, (double)t0[2*TS + 2], s);
        csc[tid] = s;
    }
    __syncthreads();

    // ---- Phase C: rank by (double desc, index asc); set keep bits for top-KSEL ----
    if (tid < ntie) {
        double mys = csc[tid];
        int   cpos = cidx[tid];
        unsigned rnk = 0;
        for (int q = 0; q < ntie; ++q) {
            double v = csc[q];
            rnk += (v > mys) || (v == mys && cidx[q] < cpos);
        }
        if (rnk < KSEL)
            atomicOr(&keepbm[cpos >> 5], 1u << (cpos & 31));
    }
    __syncthreads();

    // ---- store: pristine x from tile, masked by keep bitmap, coalesced float4 ----
    float4* go4 = reinterpret_cast<float4*>(go);
    for (int i = tid; i < (HW * HW) / 4; i += NT) {
        int p  = i * 4;
        int r  = p / HW;
        int cc = p - r * HW;
        unsigned bits = keepbm[p >> 5] >> (p & 31);   // 4 bits, same word (p%4==0)
        const float* t = &tile[(r + 1) * TS + cc + 1];
        float4 v;
        v.x = (bits & 1u) ? t[0] : 0.0f;
        v.y = (bits & 2u) ? t[1] : 0.0f;
        v.z = (bits & 4u) ? t[2] : 0.0f;
        v.w = (bits & 8u) ? t[3] : 0.0f;
        go4[i] = v;
    }
}

extern "C" void kernel_launch(void* const* d_in, const int* in_sizes, int n_in,
                              void* d_out, int out_size)
{
    const float* x  = (const float*)d_in[0];
    const float* w  = (const float*)d_in[1];
    const float* b  = (const float*)d_in[2];
    float*       o  = (float*)d_out;
    int C    = in_sizes[2];               // 384
    int n_bc = in_sizes[0] / (HW * HW);   // 12288
    topk_spatial_kernel<<<n_bc, NT>>>(x, w, b, o, C);
}

// round 10
// speedup vs baseline: 1.7323x; 1.7323x over previous
#include <cuda_runtime.h>
#include <cuda_bf16.h>

#define HW   56
#define TS   59          // padded smem row stride
#define KSEL 30
#define NT   224         // threads: 56 rows x 4 col-groups
#define NV   14          // pixels per thread (224*14 = 3136)
#define TMAX 448         // candidate capacity

__global__ __launch_bounds__(NT, 7)
void topk_spatial_kernel(const float* __restrict__ x,
                         const float* __restrict__ wgt,
                         const float* __restrict__ bias,
                         float* __restrict__ out,
                         int C)
{
    __shared__ float    tile[58 * TS];   // rows 0..57 (borders zero), stride TS
    __shared__ union {                   // radix hists and candidate arrays are
        unsigned hist[2][256];           //   temporally disjoint -> alias them
        struct { double csc[TMAX]; int cidx[TMAX]; } cand;
    } u;
    __shared__ float    wsm[10];
    __shared__ unsigned sh_dsel, sh_krem;
    __shared__ float    xmax_sm[7];
    __shared__ int      tcnt;
    __shared__ unsigned keepbm[98];      // 3136-bit keep bitmap

    const int tid = threadIdx.x;
    const int bc  = blockIdx.x;
    const int ch  = bc % C;
    const float* gx = x   + (size_t)bc * (HW * HW);
    float*       go = out + (size_t)bc * (HW * HW);

    if (tid < 9)  wsm[tid] = wgt[ch * 9 + tid];
    if (tid == 9) wsm[9]   = bias[ch];
    if (tid == 10) tcnt = 0;
    u.hist[0][tid] = 0;
    if (tid < 32) u.hist[0][tid + NT] = 0;
    if (tid < 98) keepbm[tid] = 0;

    // ---- zero borders of the 58x58 logical tile (232 words, 224 threads) ----
    for (int i = tid; i < 232; i += NT) {
        if      (i < 58)  tile[i] = 0.f;
        else if (i < 116) tile[57 * TS + (i - 58)] = 0.f;
        else if (i < 174) tile[(i - 116) * TS] = 0.f;
        else              tile[(i - 174) * TS + 57] = 0.f;
    }

    // ---- load interior (float4), tracking max|x| for the error bound ----
    float maxv = 0.0f;
    const float4* gx4 = reinterpret_cast<const float4*>(gx);
    for (int i = tid; i < (HW * HW) / 4; i += NT) {
        float4 v = gx4[i];
        maxv = fmaxf(maxv, fmaxf(fmaxf(fabsf(v.x), fabsf(v.y)),
                                 fmaxf(fabsf(v.z), fabsf(v.w))));
        int p  = i * 4;
        int r  = p / HW;
        int cc = p - r * HW;
        float* t = &tile[(r + 1) * TS + cc + 1];
        t[0] = v.x; t[1] = v.y; t[2] = v.z; t[3] = v.w;
    }
    #pragma unroll
    for (int d = 16; d > 0; d >>= 1)
        maxv = fmaxf(maxv, __shfl_xor_sync(0xFFFFFFFFu, maxv, d));
    if ((tid & 31) == 0) xmax_sm[tid >> 5] = maxv;
    __syncthreads();

    const float w0 = wsm[0], w1 = wsm[1], w2 = wsm[2];
    const float w3 = wsm[3], w4 = wsm[4], w5 = wsm[5];
    const float w6 = wsm[6], w7 = wsm[7], w8 = wsm[8];
    const float bv = wsm[9];

    const int row  = tid >> 2;            // 0..55
    const int c0   = (tid & 3) * NV;      // 0,14,28,42
    const int lane = tid & 31;

    // ---- conv pass 1: track ONLY the per-thread max score (no score array) ----
    float smax = -3.4e38f;
    {
        const float* t0 = &tile[row * TS + c0];
        const float* t1 = t0 + TS;
        const float* t2 = t1 + TS;
        float a0 = t0[0], a1 = t0[1];
        float b0 = t1[0], b1 = t1[1];
        float d0 = t2[0], d1 = t2[1];
        #pragma unroll
        for (int j = 0; j < NV; ++j) {
            float a2 = t0[j + 2], b2 = t1[j + 2], d2 = t2[j + 2];
            float s = bv;
            s = fmaf(w0, a0, s); s = fmaf(w1, a1, s); s = fmaf(w2, a2, s);
            s = fmaf(w3, b0, s); s = fmaf(w4, b1, s); s = fmaf(w5, b2, s);
            s = fmaf(w6, d0, s); s = fmaf(w7, d1, s); s = fmaf(w8, d2, s);
            smax = fmaxf(smax, s);
            a0 = a1; a1 = a2; b0 = b1; b1 = b2; d0 = d1; d1 = d2;
        }
    }
    unsigned mu = __float_as_uint(smax);
    const unsigned maxkey = mu ^ ((unsigned)(((int)mu) >> 31) | 0x80000000u);

    // ---- radix select rank-KSEL among the 224 per-thread maxima (disjoint
    //      groups => >=KSEL elements are >= M30 => band is a top-KSEL superset) ----
    unsigned prefix = 0;
    unsigned krem   = KSEL;
    #pragma unroll
    for (int pass = 0; pass < 4; ++pass) {
        const int cur   = pass & 1;
        const int shift = 24 - 8 * pass;
        {
            unsigned v  = maxkey;
            bool ok = (((unsigned long long)v) >> (shift + 8)) ==
                      (unsigned long long)prefix;
            unsigned digit = ok ? ((v >> shift) & 255u) : 0xFFFFFFFFu;
            unsigned m = __match_any_sync(0xFFFFFFFFu, digit);
            if (ok && ((__ffs(m) - 1) == lane))
                atomicAdd(&u.hist[cur][digit], (unsigned)__popc(m));
            u.hist[cur ^ 1][tid] = 0;                 // pre-zero next buffer
            if (tid < 32) u.hist[cur ^ 1][tid + NT] = 0;
        }
        __syncthreads();

        if (tid < 32) {
            unsigned loc[8];
            unsigned run = 0;
            #pragma unroll
            for (int j = 7; j >= 0; --j) { run += u.hist[cur][lane * 8 + j]; loc[j] = run; }
            unsigned laneTotal = run;
            unsigned incl = laneTotal;
            #pragma unroll
            for (int d = 1; d < 32; d <<= 1) {
                unsigned t = __shfl_down_sync(0xFFFFFFFFu, incl, d);
                if (lane + d < 32) incl += t;
            }
            unsigned hiSum = incl - laneTotal;
            #pragma unroll
            for (int j = 0; j < 8; ++j) {
                unsigned suf  = hiSum + loc[j];                         // >= bin
                unsigned sufn = (j < 7) ? (hiSum + loc[j + 1]) : hiSum; // >  bin
                if (suf >= krem && sufn < krem) {
                    sh_dsel = (unsigned)(lane * 8 + j);
                    sh_krem = krem - sufn;
                }
            }
        }
        __syncthreads();
        prefix = (prefix << 8) | sh_dsel;
        krem   = sh_krem;
    }
    const unsigned M30key = prefix;

    // ---- guard-band threshold in FLOAT space: Tc = M30 - 2E ----
    float xmax = xmax_sm[0];
    #pragma unroll
    for (int i = 1; i < 7; ++i) xmax = fmaxf(xmax, xmax_sm[i]);
    const float wsum = fabsf(w0) + fabsf(w1) + fabsf(w2) + fabsf(w3) + fabsf(w4)
                     + fabsf(w5) + fabsf(w6) + fabsf(w7) + fabsf(w8);
    const float E = (wsum * xmax + fabsf(bv)) * 1.2e-6f;   // rigorous fp32 bound

    unsigned tu = (M30key & 0x80000000u) ? (M30key ^ 0x80000000u) : ~M30key;
    const float Tc = __uint_as_float(tu) - 2.0f * E;

    // ---- Phase A: threads above the band RECOMPUTE their scores (identical
    //      expression => identical fp32) and push candidate indices ----
    if (smax >= Tc) {
        const float* t0 = &tile[row * TS + c0];
        const float* t1 = t0 + TS;
        const float* t2 = t1 + TS;
        float a0 = t0[0], a1 = t0[1];
        float b0 = t1[0], b1 = t1[1];
        float d0 = t2[0], d1 = t2[1];
        #pragma unroll
        for (int j = 0; j < NV; ++j) {
            float a2 = t0[j + 2], b2 = t1[j + 2], d2 = t2[j + 2];
            float s = bv;
            s = fmaf(w0, a0, s); s = fmaf(w1, a1, s); s = fmaf(w2, a2, s);
            s = fmaf(w3, b0, s); s = fmaf(w4, b1, s); s = fmaf(w5, b2, s);
            s = fmaf(w6, d0, s); s = fmaf(w7, d1, s); s = fmaf(w8, d2, s);
            if (s >= Tc) {
                int pos = atomicAdd(&tcnt, 1);
                if (pos < TMAX) u.cand.cidx[pos] = row * HW + c0 + j;
            }
            a0 = a1; a1 = a2; b0 = b1; b1 = b2; d0 = d1; d1 = d2;
        }
    }
    __syncthreads();
    const int ntie = (tcnt < TMAX) ? tcnt : TMAX;

    // ---- Phase B: one thread per candidate computes the EXACT double score ----
    if (tid < ntie) {
        int p = u.cand.cidx[tid];
        int r = p / HW, cc = p - r * HW;
        const float* t0 = &tile[r * TS + cc];
        double s = (double)bv;
        s = fma((double)w0, (double)t0[0],        s);
        s = fma((double)w1, (double)t0[1],        s);
        s = fma((double)w2, (double)t0[2],        s);
        s = fma((double)w3, (double)t0[TS],       s);
        s = fma((double)w4, (double)t0[TS + 1],   s);
        s = fma((double)w5, (double)t0[TS + 2],   s);
        s = fma((double)w6, (double)t0[2*TS],     s);
        s = fma((double)w7, (double)t0[2*TS + 1], s);
        s = fma((double)w8, (double)t0[2*TS + 2], s);
        u.cand.csc[tid] = s;
    }
    __syncthreads();

    // ---- Phase C: rank by (double desc, index asc); set keep bits ----
    if (tid < ntie) {
        double mys = u.cand.csc[tid];
        int   cpos = u.cand.cidx[tid];
        unsigned rnk = 0;
        for (int q = 0; q < ntie; ++q) {
            double v = u.cand.csc[q];
            rnk += (v > mys) || (v == mys && u.cand.cidx[q] < cpos);
        }
        if (rnk < KSEL)
            atomicOr(&keepbm[cpos >> 5], 1u << (cpos & 31));
    }
    __syncthreads();

    // ---- store: pristine x from tile masked by keep bitmap, coalesced ----
    float4* go4 = reinterpret_cast<float4*>(go);
    for (int i = tid; i < (HW * HW) / 4; i += NT) {
        int p  = i * 4;
        int r  = p / HW;
        int cc = p - r * HW;
        unsigned bits = keepbm[p >> 5] >> (p & 31);
        const float* t = &tile[(r + 1) * TS + cc + 1];
        float4 v;
        v.x = (bits & 1u) ? t[0] : 0.0f;
        v.y = (bits & 2u) ? t[1] : 0.0f;
        v.z = (bits & 4u) ? t[2] : 0.0f;
        v.w = (bits & 8u) ? t[3] : 0.0f;
        go4[i] = v;
    }
}

extern "C" void kernel_launch(void* const* d_in, const int* in_sizes, int n_in,
                              void* d_out, int out_size)
{
    const float* x  = (const float*)d_in[0];
    const float* w  = (const float*)d_in[1];
    const float* b  = (const float*)d_in[2];
    float*       o  = (float*)d_out;
    int C    = in_sizes[2];               // 384
    int n_bc = in_sizes[0] / (HW * HW);   // 12288
    topk_spatial_kernel<<<n_bc, NT>>>(x, w, b, o, C);
}

// round 11
// speedup vs baseline: 1.8426x; 1.0637x over previous
#include <cuda_runtime.h>
#include <cuda_bf16.h>

#define HW   56
#define TS   59          // padded smem row stride
#define KSEL 30
#define NT   224         // threads: 28 row-pairs x 8 col-groups
#define NV   7           // columns per thread patch (2 rows x 7 cols = 14 px)
#define TMAX 448         // candidate capacity

__global__ __launch_bounds__(NT, 7)
void topk_spatial_kernel(const float* __restrict__ x,
                         const float* __restrict__ wgt,
                         const float* __restrict__ bias,
                         float* __restrict__ out,
                         int C)
{
    __shared__ float    tile[58 * TS];   // rows 0..57 (borders zero), stride TS
    __shared__ union {                   // radix hists and candidate arrays are
        unsigned hist[2][256];           //   temporally disjoint -> alias them
        struct { double csc[TMAX]; int cidx[TMAX]; } cand;
    } u;
    __shared__ float    wsm[10];
    __shared__ unsigned sh_dsel, sh_krem;
    __shared__ float    xmax_sm[7];
    __shared__ int      tcnt;
    __shared__ unsigned keepbm[98];      // 3136-bit keep bitmap

    const int tid = threadIdx.x;
    const int bc  = blockIdx.x;
    const int ch  = bc % C;
    const float* gx = x   + (size_t)bc * (HW * HW);
    float*       go = out + (size_t)bc * (HW * HW);

    if (tid < 9)  wsm[tid] = wgt[ch * 9 + tid];
    if (tid == 9) wsm[9]   = bias[ch];
    if (tid == 10) tcnt = 0;
    u.hist[0][tid] = 0;
    if (tid < 32) u.hist[0][tid + NT] = 0;
    if (tid < 98) keepbm[tid] = 0;

    // ---- zero borders of the 58x58 logical tile ----
    for (int i = tid; i < 232; i += NT) {
        if      (i < 58)  tile[i] = 0.f;
        else if (i < 116) tile[57 * TS + (i - 58)] = 0.f;
        else if (i < 174) tile[(i - 116) * TS] = 0.f;
        else              tile[(i - 174) * TS + 57] = 0.f;
    }

    // ---- load interior (float4), tracking max|x| for the error bound ----
    float maxv = 0.0f;
    const float4* gx4 = reinterpret_cast<const float4*>(gx);
    for (int i = tid; i < (HW * HW) / 4; i += NT) {
        float4 v = gx4[i];
        maxv = fmaxf(maxv, fmaxf(fmaxf(fabsf(v.x), fabsf(v.y)),
                                 fmaxf(fabsf(v.z), fabsf(v.w))));
        int p  = i * 4;
        int r  = p / HW;
        int cc = p - r * HW;
        float* t = &tile[(r + 1) * TS + cc + 1];
        t[0] = v.x; t[1] = v.y; t[2] = v.z; t[3] = v.w;
    }
    #pragma unroll
    for (int d = 16; d > 0; d >>= 1)
        maxv = fmaxf(maxv, __shfl_xor_sync(0xFFFFFFFFu, maxv, d));
    if ((tid & 31) == 0) xmax_sm[tid >> 5] = maxv;
    __syncthreads();

    const float w0 = wsm[0], w1 = wsm[1], w2 = wsm[2];
    const float w3 = wsm[3], w4 = wsm[4], w5 = wsm[5];
    const float w6 = wsm[6], w7 = wsm[7], w8 = wsm[8];
    const float bv = wsm[9];

    const int row0 = (tid >> 3) * 2;      // 0,2,...,54 (pixel row pair)
    const int c0   = (tid & 7) * NV;      // 0,7,...,49
    const int lane = tid & 31;

    // ---- conv pass 1: 2x7 patch per thread; track ONLY the running max.
    //      Pixel (r,c) taps tile rows r..r+2, cols c..c+2. Patch reads 4x9. ----
    float smax = -3.4e38f;
    {
        const float* R0 = &tile[row0 * TS + c0];
        const float* R1 = R0 + TS;
        const float* R2 = R1 + TS;
        const float* R3 = R2 + TS;
        float a00 = R0[0], a01 = R0[1];
        float a10 = R1[0], a11 = R1[1];
        float a20 = R2[0], a21 = R2[1];
        float a30 = R3[0], a31 = R3[1];
        #pragma unroll
        for (int j = 0; j < NV; ++j) {
            float a02 = R0[j + 2], a12 = R1[j + 2];
            float a22 = R2[j + 2], a32 = R3[j + 2];
            float s0 = bv;                              // pixel (row0, c0+j)
            s0 = fmaf(w0, a00, s0); s0 = fmaf(w1, a01, s0); s0 = fmaf(w2, a02, s0);
            s0 = fmaf(w3, a10, s0); s0 = fmaf(w4, a11, s0); s0 = fmaf(w5, a12, s0);
            s0 = fmaf(w6, a20, s0); s0 = fmaf(w7, a21, s0); s0 = fmaf(w8, a22, s0);
            float s1 = bv;                              // pixel (row0+1, c0+j)
            s1 = fmaf(w0, a10, s1); s1 = fmaf(w1, a11, s1); s1 = fmaf(w2, a12, s1);
            s1 = fmaf(w3, a20, s1); s1 = fmaf(w4, a21, s1); s1 = fmaf(w5, a22, s1);
            s1 = fmaf(w6, a30, s1); s1 = fmaf(w7, a31, s1); s1 = fmaf(w8, a32, s1);
            smax = fmaxf(smax, fmaxf(s0, s1));
            a00 = a01; a01 = a02; a10 = a11; a11 = a12;
            a20 = a21; a21 = a22; a30 = a31; a31 = a32;
        }
    }
    unsigned mu = __float_as_uint(smax);
    const unsigned maxkey = mu ^ ((unsigned)(((int)mu) >> 31) | 0x80000000u);

    // ---- radix select rank-KSEL among the 224 per-thread maxima (disjoint
    //      groups => >=KSEL elements are >= M30 => band is a top-KSEL superset) ----
    unsigned prefix = 0;
    unsigned krem   = KSEL;
    #pragma unroll
    for (int pass = 0; pass < 4; ++pass) {
        const int cur   = pass & 1;
        const int shift = 24 - 8 * pass;
        {
            unsigned v  = maxkey;
            bool ok = (((unsigned long long)v) >> (shift + 8)) ==
                      (unsigned long long)prefix;
            unsigned digit = ok ? ((v >> shift) & 255u) : 0xFFFFFFFFu;
            unsigned m = __match_any_sync(0xFFFFFFFFu, digit);
            if (ok && ((__ffs(m) - 1) == lane))
                atomicAdd(&u.hist[cur][digit], (unsigned)__popc(m));
            u.hist[cur ^ 1][tid] = 0;                 // pre-zero next buffer
            if (tid < 32) u.hist[cur ^ 1][tid + NT] = 0;
        }
        __syncthreads();

        if (tid < 32) {
            unsigned loc[8];
            unsigned run = 0;
            #pragma unroll
            for (int j = 7; j >= 0; --j) { run += u.hist[cur][lane * 8 + j]; loc[j] = run; }
            unsigned laneTotal = run;
            unsigned incl = laneTotal;
            #pragma unroll
            for (int d = 1; d < 32; d <<= 1) {
                unsigned t = __shfl_down_sync(0xFFFFFFFFu, incl, d);
                if (lane + d < 32) incl += t;
            }
            unsigned hiSum = incl - laneTotal;
            #pragma unroll
            for (int j = 0; j < 8; ++j) {
                unsigned suf  = hiSum + loc[j];                         // >= bin
                unsigned sufn = (j < 7) ? (hiSum + loc[j + 1]) : hiSum; // >  bin
                if (suf >= krem && sufn < krem) {
                    sh_dsel = (unsigned)(lane * 8 + j);
                    sh_krem = krem - sufn;
                }
            }
        }
        __syncthreads();
        prefix = (prefix << 8) | sh_dsel;
        krem   = sh_krem;
    }
    const unsigned M30key = prefix;

    // ---- guard-band threshold in FLOAT space: Tc = M30 - 2E ----
    float xmax = xmax_sm[0];
    #pragma unroll
    for (int i = 1; i < 7; ++i) xmax = fmaxf(xmax, xmax_sm[i]);
    const float wsum = fabsf(w0) + fabsf(w1) + fabsf(w2) + fabsf(w3) + fabsf(w4)
                     + fabsf(w5) + fabsf(w6) + fabsf(w7) + fabsf(w8);
    const float E = (wsum * xmax + fabsf(bv)) * 1.2e-6f;   // rigorous fp32 bound

    unsigned tu = (M30key & 0x80000000u) ? (M30key ^ 0x80000000u) : ~M30key;
    const float Tc = __uint_as_float(tu) - 2.0f * E;

    // ---- Phase A: threads above the band RECOMPUTE their patch scores
    //      (identical per-pixel fmaf chain => identical fp32) ----
    if (smax >= Tc) {
        const float* R0 = &tile[row0 * TS + c0];
        const float* R1 = R0 + TS;
        const float* R2 = R1 + TS;
        const float* R3 = R2 + TS;
        float a00 = R0[0], a01 = R0[1];
        float a10 = R1[0], a11 = R1[1];
        float a20 = R2[0], a21 = R2[1];
        float a30 = R3[0], a31 = R3[1];
        #pragma unroll
        for (int j = 0; j < NV; ++j) {
            float a02 = R0[j + 2], a12 = R1[j + 2];
            float a22 = R2[j + 2], a32 = R3[j + 2];
            float s0 = bv;
            s0 = fmaf(w0, a00, s0); s0 = fmaf(w1, a01, s0); s0 = fmaf(w2, a02, s0);
            s0 = fmaf(w3, a10, s0); s0 = fmaf(w4, a11, s0); s0 = fmaf(w5, a12, s0);
            s0 = fmaf(w6, a20, s0); s0 = fmaf(w7, a21, s0); s0 = fmaf(w8, a22, s0);
            float s1 = bv;
            s1 = fmaf(w0, a10, s1); s1 = fmaf(w1, a11, s1); s1 = fmaf(w2, a12, s1);
            s1 = fmaf(w3, a20, s1); s1 = fmaf(w4, a21, s1); s1 = fmaf(w5, a22, s1);
            s1 = fmaf(w6, a30, s1); s1 = fmaf(w7, a31, s1); s1 = fmaf(w8, a32, s1);
            if (s0 >= Tc) {
                int pos = atomicAdd(&tcnt, 1);
                if (pos < TMAX) u.cand.cidx[pos] = row0 * HW + c0 + j;
            }
            if (s1 >= Tc) {
                int pos = atomicAdd(&tcnt, 1);
                if (pos < TMAX) u.cand.cidx[pos] = (row0 + 1) * HW + c0 + j;
            }
            a00 = a01; a01 = a02; a10 = a11; a11 = a12;
            a20 = a21; a21 = a22; a30 = a31; a31 = a32;
        }
    }
    __syncthreads();
    const int ntie = (tcnt < TMAX) ? tcnt : TMAX;

    // ---- Phase B: one thread per candidate computes the EXACT double score ----
    if (tid < ntie) {
        int p = u.cand.cidx[tid];
        int r = p / HW, cc = p - r * HW;
        const float* t0 = &tile[r * TS + cc];
        double s = (double)bv;
        s = fma((double)w0, (double)t0[0],        s);
        s = fma((double)w1, (double)t0[1],        s);
        s = fma((double)w2, (double)t0[2],        s);
        s = fma((double)w3, (double)t0[TS],       s);
        s = fma((double)w4, (double)t0[TS + 1],   s);
        s = fma((double)w5, (double)t0[TS + 2],   s);
        s = fma((double)w6, (double)t0[2*TS],     s);
        s = fma((double)w7, (double)t0[2*TS + 1], s);
        s = fma((double)w8, (double)t0[2*TS + 2], s);
        u.cand.csc[tid] = s;
    }
    __syncthreads();

    // ---- Phase C: rank by (double desc, index asc); set keep bits ----
    if (tid < ntie) {
        double mys = u.cand.csc[tid];
        int   cpos = u.cand.cidx[tid];
        unsigned rnk = 0;
        for (int q = 0; q < ntie; ++q) {
            double v = u.cand.csc[q];
            rnk += (v > mys) || (v == mys && u.cand.cidx[q] < cpos);
        }
        if (rnk < KSEL)
            atomicOr(&keepbm[cpos >> 5], 1u << (cpos & 31));
    }
    __syncthreads();

    // ---- store: pristine x from tile masked by keep bitmap, coalesced ----
    float4* go4 = reinterpret_cast<float4*>(go);
    for (int i = tid; i < (HW * HW) / 4; i += NT) {
        int p  = i * 4;
        int r  = p / HW;
        int cc = p - r * HW;
        unsigned bits = keepbm[p >> 5] >> (p & 31);
        const float* t = &tile[(r + 1) * TS + cc + 1];
        float4 v;
        v.x = (bits & 1u) ? t[0] : 0.0f;
        v.y = (bits & 2u) ? t[1] : 0.0f;
        v.z = (bits & 4u) ? t[2] : 0.0f;
        v.w = (bits & 8u) ? t[3] : 0.0f;
        go4[i] = v;
    }
}

extern "C" void kernel_launch(void* const* d_in, const int* in_sizes, int n_in,
                              void* d_out, int out_size)
{
    const float* x  = (const float*)d_in[0];
    const float* w  = (const float*)d_in[1];
    const float* b  = (const float*)d_in[2];
    float*       o  = (float*)d_out;
    int C    = in_sizes[2];               // 384
    int n_bc = in_sizes[0] / (HW * HW);   // 12288
    topk_spatial_kernel<<<n_bc, NT>>>(x, w, b, o, C);
}

// round 13
// speedup vs baseline: 1.9669x; 1.0674x over previous
#include <cuda_runtime.h>
#include <cuda_bf16.h>

#define HW   56
#define TS   68          // row stride: 4-aligned for vec ops, conflict-free conv
#define KSEL 30
#define NT   224         // threads: 28 row-pairs x 8 col-groups
#define NV   7           // columns per thread patch (2 rows x 7 cols = 14 px)
#define TMAX 448         // candidate capacity

__global__ __launch_bounds__(NT, 7)
void topk_spatial_kernel(const float* __restrict__ x,
                         const float* __restrict__ wgt,
                         const float* __restrict__ bias,
                         float* __restrict__ out,
                         int C)
{
    __shared__ float    tile[58 * TS];   // pixel (r,c) at [(r+1)*TS + c+4]
    __shared__ union {                   // hists / candidate arrays: disjoint in time
        unsigned hist[2][256];
        struct { double csc[TMAX]; int cidx[TMAX]; } cand;
    } u;
    __shared__ float    wsm[10];
    __shared__ unsigned sh_dsel, sh_krem;
    __shared__ float    xmax_sm[7];
    __shared__ int      tcnt, pcnt;
    __shared__ int      plist[NT];       // tids whose max clears the band
    __shared__ unsigned keepbm[98];      // 3136-bit keep bitmap

    const int tid = threadIdx.x;
    const int bc  = blockIdx.x;
    const int ch  = bc % C;
    const float* gx = x   + (size_t)bc * (HW * HW);
    float*       go = out + (size_t)bc * (HW * HW);

    if (tid < 9)  wsm[tid] = wgt[ch * 9 + tid];
    if (tid == 9) wsm[9]   = bias[ch];
    if (tid == 10) tcnt = 0;
    if (tid == 11) pcnt = 0;
    u.hist[0][tid] = 0;
    if (tid < 32) u.hist[0][tid + NT] = 0;
    if (tid < 98) keepbm[tid] = 0;

    // ---- zero borders: rows 0 & 57 (full), cols 3 & 60 (rows 1..56) ----
    for (int i = tid; i < 248; i += NT) {
        if      (i < 68)  tile[i] = 0.f;
        else if (i < 136) tile[57 * TS + (i - 68)] = 0.f;
        else if (i < 192) tile[(i - 135) * TS + 3] = 0.f;
        else              tile[(i - 191) * TS + 60] = 0.f;
    }

    // ---- load interior: vectorized STS.128, tracking max|x| ----
    float maxv = 0.0f;
    const float4* gx4 = reinterpret_cast<const float4*>(gx);
    for (int i = tid; i < (HW * HW) / 4; i += NT) {
        float4 v = gx4[i];
        maxv = fmaxf(maxv, fmaxf(fmaxf(fabsf(v.x), fabsf(v.y)),
                                 fmaxf(fabsf(v.z), fabsf(v.w))));
        int p  = i * 4;
        int r  = p / HW;
        int cc = p - r * HW;
        *reinterpret_cast<float4*>(&tile[(r + 1) * TS + cc + 4]) = v;
    }
    #pragma unroll
    for (int d = 16; d > 0; d >>= 1)
        maxv = fmaxf(maxv, __shfl_xor_sync(0xFFFFFFFFu, maxv, d));
    if ((tid & 31) == 0) xmax_sm[tid >> 5] = maxv;
    __syncthreads();

    const float w0 = wsm[0], w1 = wsm[1], w2 = wsm[2];
    const float w3 = wsm[3], w4 = wsm[4], w5 = wsm[5];
    const float w6 = wsm[6], w7 = wsm[7], w8 = wsm[8];
    const float bv = wsm[9];

    const int row0 = (tid >> 3) * 2;      // 0,2,...,54
    const int c0   = (tid & 7) * NV;      // 0,7,...,49
    const int lane = tid & 31;

    // ---- conv pass 1: 2x7 patch, rolling window; track ONLY the max ----
    float smax = -3.4e38f;
    {
        const float* R0 = &tile[row0 * TS + c0 + 3];
        const float* R1 = R0 + TS;
        const float* R2 = R1 + TS;
        const float* R3 = R2 + TS;
        float a00 = R0[0], a01 = R0[1];
        float a10 = R1[0], a11 = R1[1];
        float a20 = R2[0], a21 = R2[1];
        float a30 = R3[0], a31 = R3[1];
        #pragma unroll
        for (int j = 0; j < NV; ++j) {
            float a02 = R0[j + 2], a12 = R1[j + 2];
            float a22 = R2[j + 2], a32 = R3[j + 2];
            float s0 = bv;
            s0 = fmaf(w0, a00, s0); s0 = fmaf(w1, a01, s0); s0 = fmaf(w2, a02, s0);
            s0 = fmaf(w3, a10, s0); s0 = fmaf(w4, a11, s0); s0 = fmaf(w5, a12, s0);
            s0 = fmaf(w6, a20, s0); s0 = fmaf(w7, a21, s0); s0 = fmaf(w8, a22, s0);
            float s1 = bv;
            s1 = fmaf(w0, a10, s1); s1 = fmaf(w1, a11, s1); s1 = fmaf(w2, a12, s1);
            s1 = fmaf(w3, a20, s1); s1 = fmaf(w4, a21, s1); s1 = fmaf(w5, a22, s1);
            s1 = fmaf(w6, a30, s1); s1 = fmaf(w7, a31, s1); s1 = fmaf(w8, a32, s1);
            smax = fmaxf(smax, fmaxf(s0, s1));
            a00 = a01; a01 = a02; a10 = a11; a11 = a12;
            a20 = a21; a21 = a22; a30 = a31; a31 = a32;
        }
    }
    unsigned mu = __float_as_uint(smax);
    const unsigned maxkey = mu ^ ((unsigned)(((int)mu) >> 31) | 0x80000000u);

    // ---- radix select rank-KSEL among the 224 per-thread maxima ----
    unsigned prefix = 0;
    unsigned krem   = KSEL;
    #pragma unroll
    for (int pass = 0; pass < 4; ++pass) {
        const int cur   = pass & 1;
        const int shift = 24 - 8 * pass;
        {
            unsigned v  = maxkey;
            bool ok = (((unsigned long long)v) >> (shift + 8)) ==
                      (unsigned long long)prefix;
            unsigned digit = ok ? ((v >> shift) & 255u) : 0xFFFFFFFFu;
            unsigned m = __match_any_sync(0xFFFFFFFFu, digit);
            if (ok && ((__ffs(m) - 1) == lane))
                atomicAdd(&u.hist[cur][digit], (unsigned)__popc(m));
            u.hist[cur ^ 1][tid] = 0;
            if (tid < 32) u.hist[cur ^ 1][tid + NT] = 0;
        }
        __syncthreads();

        if (tid < 32) {
            unsigned loc[8];
            unsigned run = 0;
            #pragma unroll
            for (int j = 7; j >= 0; --j) { run += u.hist[cur][lane * 8 + j]; loc[j] = run; }
            unsigned laneTotal = run;
            unsigned incl = laneTotal;
            #pragma unroll
            for (int d = 1; d < 32; d <<= 1) {
                unsigned t = __shfl_down_sync(0xFFFFFFFFu, incl, d);
                if (lane + d < 32) incl += t;
            }
            unsigned hiSum = incl - laneTotal;
            #pragma unroll
            for (int j = 0; j < 8; ++j) {
                unsigned suf  = hiSum + loc[j];
                unsigned sufn = (j < 7) ? (hiSum + loc[j + 1]) : hiSum;
                if (suf >= krem && sufn < krem) {
                    sh_dsel = (unsigned)(lane * 8 + j);
                    sh_krem = krem - sufn;
                }
            }
        }
        __syncthreads();
        prefix = (prefix << 8) | sh_dsel;
        krem   = sh_krem;
    }
    const unsigned M30key = prefix;

    // ---- guard band: Tc = M30 - 2E; valid for ANY recompute order with err<=E ----
    float xmax = xmax_sm[0];
    #pragma unroll
    for (int i = 1; i < 7; ++i) xmax = fmaxf(xmax, xmax_sm[i]);
    const float wsum = fabsf(w0) + fabsf(w1) + fabsf(w2) + fabsf(w3) + fabsf(w4)
                     + fabsf(w5) + fabsf(w6) + fabsf(w7) + fabsf(w8);
    const float E = (wsum * xmax + fabsf(bv)) * 1.2e-6f;

    unsigned tu = (M30key & 0x80000000u) ? (M30key ^ 0x80000000u) : ~M30key;
    const float Tc = __uint_as_float(tu) - 2.0f * E;

    // ---- Phase A0: passing threads publish tid (one atomic each) ----
    if (smax >= Tc) {
        int q = atomicAdd(&pcnt, 1);
        plist[q] = tid;                    // q < 224 always
    }
    __syncthreads();
    const int np = pcnt;

    // ---- Phase A1: COOPERATIVE rescore of the ~np*14 flagged pixels.
    //      Uniform across all threads; any fp32 order works (err <= E). ----
    for (int idx = tid; idx < np * 14; idx += NT) {
        int q     = idx / 14;
        int k     = idx - q * 14;
        int owner = plist[q];
        int pr    = ((owner >> 3) * 2) + (k >= NV ? 1 : 0);
        int pc    = ((owner & 7) * NV) + (k >= NV ? k - NV : k);
        const float* t0 = &tile[pr * TS + pc + 3];
        float s = bv;
        s = fmaf(w0, t0[0],        s);
        s = fmaf(w1, t0[1],        s);
        s = fmaf(w2, t0[2],        s);
        s = fmaf(w3, t0[TS],       s);
        s = fmaf(w4, t0[TS + 1],   s);
        s = fmaf(w5, t0[TS + 2],   s);
        s = fmaf(w6, t0[2*TS],     s);
        s = fmaf(w7, t0[2*TS + 1], s);
        s = fmaf(w8, t0[2*TS + 2], s);
        if (s >= Tc) {
            int pos = atomicAdd(&tcnt, 1);
            if (pos < TMAX) u.cand.cidx[pos] = pr * HW + pc;
        }
    }
    __syncthreads();
    const int ntie = (tcnt < TMAX) ? tcnt : TMAX;

    // ---- Phase B: one thread per candidate computes the EXACT double score ----
    if (tid < ntie) {
        int p = u.cand.cidx[tid];
        int r = p / HW, cc = p - r * HW;
        const float* t0 = &tile[r * TS + cc + 3];
        double s = (double)bv;
        s = fma((double)w0, (double)t0[0],        s);
        s = fma((double)w1, (double)t0[1],        s);
        s = fma((double)w2, (double)t0[2],        s);
        s = fma((double)w3, (double)t0[TS],       s);
        s = fma((double)w4, (double)t0[TS + 1],   s);
        s = fma((double)w5, (double)t0[TS + 2],   s);
        s = fma((double)w6, (double)t0[2*TS],     s);
        s = fma((double)w7, (double)t0[2*TS + 1], s);
        s = fma((double)w8, (double)t0[2*TS + 2], s);
        u.cand.csc[tid] = s;
    }
    __syncthreads();

    // ---- Phase C: rank by (double desc, index asc); set keep bits ----
    if (tid < ntie) {
        double mys = u.cand.csc[tid];
        int   cpos = u.cand.cidx[tid];
        unsigned rnk = 0;
        for (int q = 0; q < ntie; ++q) {
            double v = u.cand.csc[q];
            rnk += (v > mys) || (v == mys && u.cand.cidx[q] < cpos);
        }
        if (rnk < KSEL)
            atomicOr(&keepbm[cpos >> 5], 1u << (cpos & 31));
    }
    __syncthreads();

    // ---- store: LDS.128 from tile, masked by keep bitmap, STG.128 ----
    float4* go4 = reinterpret_cast<float4*>(go);
    for (int i = tid; i < (HW * HW) / 4; i += NT) {
        int p  = i * 4;
        int r  = p / HW;
        int cc = p - r * HW;
        unsigned bits = keepbm[p >> 5] >> (p & 31);
        float4 v = *reinterpret_cast<const float4*>(&tile[(r + 1) * TS + cc + 4]);
        v.x = (bits & 1u) ? v.x : 0.0f;
        v.y = (bits & 2u) ? v.y : 0.0f;
        v.z = (bits & 4u) ? v.z : 0.0f;
        v.w = (bits & 8u) ? v.w : 0.0f;
        go4[i] = v;
    }
}

extern "C" void kernel_launch(void* const* d_in, const int* in_sizes, int n_in,
                              void* d_out, int out_size)
{
    const float* x  = (const float*)d_in[0];
    const float* w  = (const float*)d_in[1];
    const float* b  = (const float*)d_in[2];
    float*       o  = (float*)d_out;
    int C    = in_sizes[2];               // 384
    int n_bc = in_sizes[0] / (HW * HW);   // 12288
    topk_spatial_kernel<<<n_bc, NT>>>(x, w, b, o, C);
}

// round 14
// speedup vs baseline: 2.1039x; 1.0696x over previous
#include <cuda_runtime.h>
#include <cuda_bf16.h>

#define HW   56
#define TS   68          // row stride: 4-aligned for vec ops, conflict-free conv
#define KSEL 30
#define NT   224         // threads: 28 row-pairs x 8 col-groups
#define NV   7           // columns per thread patch (2 rows x 7 cols = 14 px)
#define TMAX 448         // candidate capacity

__global__ __launch_bounds__(NT, 8)
void topk_spatial_kernel(const float* __restrict__ x,
                         const float* __restrict__ wgt,
                         const float* __restrict__ bias,
                         float* __restrict__ out,
                         int C)
{
    __shared__ float    tile[58 * TS];   // pixel (r,c) at [(r+1)*TS + c+4]
    __shared__ union {                   // hists / candidate arrays: disjoint in time
        unsigned hist[2][256];
        struct { double csc[TMAX]; int cidx[TMAX]; } cand;
    } u;
    __shared__ float    wsm[10];
    __shared__ unsigned sh_dsel, sh_krem;
    __shared__ float    xmax_sm[7];
    __shared__ int      tcnt, pcnt;
    __shared__ int      plist[NT];       // tids whose max clears the band
    __shared__ unsigned keepbm[98];      // 3136-bit keep bitmap

    const int tid = threadIdx.x;
    const int bc  = blockIdx.x;
    const int ch  = bc % C;
    const float* gx = x   + (size_t)bc * (HW * HW);
    float*       go = out + (size_t)bc * (HW * HW);

    if (tid < 9)  wsm[tid] = wgt[ch * 9 + tid];
    if (tid == 9) wsm[9]   = bias[ch];
    if (tid == 10) tcnt = 0;
    if (tid == 11) pcnt = 0;
    u.hist[0][tid] = 0;
    if (tid < 32) u.hist[0][tid + NT] = 0;
    if (tid < 98) keepbm[tid] = 0;

    // ---- zero borders: rows 0 & 57 (full), cols 3 & 60 (rows 1..56) ----
    for (int i = tid; i < 248; i += NT) {
        if      (i < 68)  tile[i] = 0.f;
        else if (i < 136) tile[57 * TS + (i - 68)] = 0.f;
        else if (i < 192) tile[(i - 135) * TS + 3] = 0.f;
        else              tile[(i - 191) * TS + 60] = 0.f;
    }

    // ---- load interior: division-free strided walk (224 = 16 rows of float4s) ----
    //      tid = 14*r0 + q : rows r0, r0+16, r0+32 always; r0+48 iff r0 < 8
    const int r0 = tid / 14;
    const int q4 = tid - r0 * 14;        // float4 index in row, col = 4*q4
    float maxv = 0.0f;
    {
        const float4* gp = reinterpret_cast<const float4*>(gx) + (r0 * 14 + q4);
        float*        tp = &tile[(r0 + 1) * TS + q4 * 4 + 4];
        #pragma unroll
        for (int it = 0; it < 4; ++it) {
            if (it < 3 || r0 < 8) {
                float4 v = *gp;
                maxv = fmaxf(maxv, fmaxf(fmaxf(fabsf(v.x), fabsf(v.y)),
                                         fmaxf(fabsf(v.z), fabsf(v.w))));
                *reinterpret_cast<float4*>(tp) = v;
            }
            gp += 16 * 14;
            tp += 16 * TS;
        }
    }
    #pragma unroll
    for (int d = 16; d > 0; d >>= 1)
        maxv = fmaxf(maxv, __shfl_xor_sync(0xFFFFFFFFu, maxv, d));
    if ((tid & 31) == 0) xmax_sm[tid >> 5] = maxv;
    __syncthreads();

    const float w0 = wsm[0], w1 = wsm[1], w2 = wsm[2];
    const float w3 = wsm[3], w4 = wsm[4], w5 = wsm[5];
    const float w6 = wsm[6], w7 = wsm[7], w8 = wsm[8];
    const float bv = wsm[9];

    const int row0 = (tid >> 3) * 2;      // 0,2,...,54
    const int c0   = (tid & 7) * NV;      // 0,7,...,49
    const int lane = tid & 31;

    // ---- conv pass 1: 2x7 patch, rolling window; track ONLY the max ----
    float smax = -3.4e38f;
    {
        const float* R0 = &tile[row0 * TS + c0 + 3];
        const float* R1 = R0 + TS;
        const float* R2 = R1 + TS;
        const float* R3 = R2 + TS;
        float a00 = R0[0], a01 = R0[1];
        float a10 = R1[0], a11 = R1[1];
        float a20 = R2[0], a21 = R2[1];
        float a30 = R3[0], a31 = R3[1];
        #pragma unroll
        for (int j = 0; j < NV; ++j) {
            float a02 = R0[j + 2], a12 = R1[j + 2];
            float a22 = R2[j + 2], a32 = R3[j + 2];
            float s0 = bv;
            s0 = fmaf(w0, a00, s0); s0 = fmaf(w1, a01, s0); s0 = fmaf(w2, a02, s0);
            s0 = fmaf(w3, a10, s0); s0 = fmaf(w4, a11, s0); s0 = fmaf(w5, a12, s0);
            s0 = fmaf(w6, a20, s0); s0 = fmaf(w7, a21, s0); s0 = fmaf(w8, a22, s0);
            float s1 = bv;
            s1 = fmaf(w0, a10, s1); s1 = fmaf(w1, a11, s1); s1 = fmaf(w2, a12, s1);
            s1 = fmaf(w3, a20, s1); s1 = fmaf(w4, a21, s1); s1 = fmaf(w5, a22, s1);
            s1 = fmaf(w6, a30, s1); s1 = fmaf(w7, a31, s1); s1 = fmaf(w8, a32, s1);
            smax = fmaxf(smax, fmaxf(s0, s1));
            a00 = a01; a01 = a02; a10 = a11; a11 = a12;
            a20 = a21; a21 = a22; a30 = a31; a31 = a32;
        }
    }
    unsigned mu = __float_as_uint(smax);
    const unsigned maxkey = mu ^ ((unsigned)(((int)mu) >> 31) | 0x80000000u);

    // ---- 3-pass radix: 24-bit prefix of the rank-KSEL maximum.
    //      trunc24(M30) <= M30, so the band below stays a top-KSEL superset. ----
    unsigned prefix = 0;
    unsigned krem   = KSEL;
    #pragma unroll
    for (int pass = 0; pass < 3; ++pass) {
        const int cur   = pass & 1;
        const int shift = 24 - 8 * pass;
        {
            unsigned v  = maxkey;
            bool ok = (((unsigned long long)v) >> (shift + 8)) ==
                      (unsigned long long)prefix;
            unsigned digit = ok ? ((v >> shift) & 255u) : 0xFFFFFFFFu;
            unsigned m = __match_any_sync(0xFFFFFFFFu, digit);
            if (ok && ((__ffs(m) - 1) == lane))
                atomicAdd(&u.hist[cur][digit], (unsigned)__popc(m));
            if (pass < 2) {                       // pre-zero next buffer
                u.hist[cur ^ 1][tid] = 0;
                if (tid < 32) u.hist[cur ^ 1][tid + NT] = 0;
            }
        }
        __syncthreads();

        if (tid < 32) {
            unsigned loc[8];
            unsigned run = 0;
            #pragma unroll
            for (int j = 7; j >= 0; --j) { run += u.hist[cur][lane * 8 + j]; loc[j] = run; }
            unsigned laneTotal = run;
            unsigned incl = laneTotal;
            #pragma unroll
            for (int d = 1; d < 32; d <<= 1) {
                unsigned t = __shfl_down_sync(0xFFFFFFFFu, incl, d);
                if (lane + d < 32) incl += t;
            }
            unsigned hiSum = incl - laneTotal;
            #pragma unroll
            for (int j = 0; j < 8; ++j) {
                unsigned suf  = hiSum + loc[j];
                unsigned sufn = (j < 7) ? (hiSum + loc[j + 1]) : hiSum;
                if (suf >= krem && sufn < krem) {
                    sh_dsel = (unsigned)(lane * 8 + j);
                    sh_krem = krem - sufn;
                }
            }
        }
        __syncthreads();
        prefix = (prefix << 8) | sh_dsel;
        krem   = sh_krem;
    }
    const unsigned MtruncKey = prefix << 8;     // lower bound of M30's key block

    // ---- guard band: Tc = float(trunc24) - 2E ----
    float xmax = xmax_sm[0];
    #pragma unroll
    for (int i = 1; i < 7; ++i) xmax = fmaxf(xmax, xmax_sm[i]);
    const float wsum = fabsf(w0) + fabsf(w1) + fabsf(w2) + fabsf(w3) + fabsf(w4)
                     + fabsf(w5) + fabsf(w6) + fabsf(w7) + fabsf(w8);
    const float E = (wsum * xmax + fabsf(bv)) * 1.2e-6f;

    unsigned tu = (MtruncKey & 0x80000000u) ? (MtruncKey ^ 0x80000000u) : ~MtruncKey;
    const float Tc = __uint_as_float(tu) - 2.0f * E;

    // ---- Phase A0: passing threads publish tid (one atomic each) ----
    if (smax >= Tc) {
        int qq = atomicAdd(&pcnt, 1);
        plist[qq] = tid;                   // qq < 224 always
    }
    __syncthreads();
    const int np = pcnt;

    // ---- Phase A1 (+fused B): cooperative rescore of flagged pixels; on a hit,
    //      the 9 taps are in registers -> compute the EXACT double score now. ----
    for (int idx = tid; idx < np * 14; idx += NT) {
        int qq    = idx / 14;
        int k     = idx - qq * 14;
        int owner = plist[qq];
        int pr    = ((owner >> 3) * 2) + (k >= NV ? 1 : 0);
        int pc    = ((owner & 7) * NV) + (k >= NV ? k - NV : k);
        const float* t0 = &tile[pr * TS + pc + 3];
        float v0 = t0[0],      v1 = t0[1],      v2 = t0[2];
        float v3 = t0[TS],     v4 = t0[TS + 1], v5 = t0[TS + 2];
        float v6 = t0[2*TS],   v7 = t0[2*TS+1], v8 = t0[2*TS+2];
        float s = bv;
        s = fmaf(w0, v0, s); s = fmaf(w1, v1, s); s = fmaf(w2, v2, s);
        s = fmaf(w3, v3, s); s = fmaf(w4, v4, s); s = fmaf(w5, v5, s);
        s = fmaf(w6, v6, s); s = fmaf(w7, v7, s); s = fmaf(w8, v8, s);
        if (s >= Tc) {
            double d = (double)bv;
            d = fma((double)w0, (double)v0, d);
            d = fma((double)w1, (double)v1, d);
            d = fma((double)w2, (double)v2, d);
            d = fma((double)w3, (double)v3, d);
            d = fma((double)w4, (double)v4, d);
            d = fma((double)w5, (double)v5, d);
            d = fma((double)w6, (double)v6, d);
            d = fma((double)w7, (double)v7, d);
            d = fma((double)w8, (double)v8, d);
            int pos = atomicAdd(&tcnt, 1);
            if (pos < TMAX) { u.cand.csc[pos] = d; u.cand.cidx[pos] = pr * HW + pc; }
        }
    }
    __syncthreads();
    const int ntie = (tcnt < TMAX) ? tcnt : TMAX;

    // ---- Phase C: rank by (double desc, index asc); set keep bits ----
    if (tid < ntie) {
        double mys = u.cand.csc[tid];
        int   cpos = u.cand.cidx[tid];
        unsigned rnk = 0;
        for (int qq = 0; qq < ntie; ++qq) {
            double v = u.cand.csc[qq];
            rnk += (v > mys) || (v == mys && u.cand.cidx[qq] < cpos);
        }
        if (rnk < KSEL)
            atomicOr(&keepbm[cpos >> 5], 1u << (cpos & 31));
    }
    __syncthreads();

    // ---- store: division-free strided walk, LDS.128 + mask + STG.128 ----
    {
        float4*      gp = reinterpret_cast<float4*>(go) + (r0 * 14 + q4);
        const float* tp = &tile[(r0 + 1) * TS + q4 * 4 + 4];
        int          p  = (r0 * 14 + q4) * 4;
        #pragma unroll
        for (int it = 0; it < 4; ++it) {
            if (it < 3 || r0 < 8) {
                unsigned bits = keepbm[p >> 5] >> (p & 31);
                float4 v = *reinterpret_cast<const float4*>(tp);
                v.x = (bits & 1u) ? v.x : 0.0f;
                v.y = (bits & 2u) ? v.y : 0.0f;
                v.z = (bits & 4u) ? v.z : 0.0f;
                v.w = (bits & 8u) ? v.w : 0.0f;
                *gp = v;
            }
            gp += 16 * 14;
            tp += 16 * TS;
            p  += 16 * 14 * 4;
        }
    }
}

extern "C" void kernel_launch(void* const* d_in, const int* in_sizes, int n_in,
                              void* d_out, int out_size)
{
    const float* x  = (const float*)d_in[0];
    const float* w  = (const float*)d_in[1];
    const float* b  = (const float*)d_in[2];
    float*       o  = (float*)d_out;
    int C    = in_sizes[2];               // 384
    int n_bc = in_sizes[0] / (HW * HW);   // 12288
    topk_spatial_kernel<<<n_bc, NT>>>(x, w, b, o, C);
}

// round 15
// speedup vs baseline: 2.2695x; 1.0787x over previous
#include <cuda_runtime.h>
#include <cuda_bf16.h>

#define HW   56
#define TS   68          // row stride: 4-aligned for vec ops, conflict-free conv
#define KSEL 30
#define NT   224         // threads: 28 row-pairs x 8 col-groups
#define NV   7           // columns per thread patch (2 rows x 7 cols = 14 px)
#define TMAX 448         // candidate capacity

__global__ __launch_bounds__(NT, 8)
void topk_spatial_kernel(const float* __restrict__ x,
                         const float* __restrict__ wgt,
                         const float* __restrict__ bias,
                         float* __restrict__ out,
                         int C)
{
    __shared__ float    tile[58 * TS];   // pixel (r,c) at [(r+1)*TS + c+4]
    __shared__ union {                   // hists / candidate arrays: disjoint in time
        unsigned hist[2][256];
        struct { double csc[TMAX]; int cidx[TMAX]; } cand;
    } u;
    __shared__ float    wsm[10];
    __shared__ unsigned sh_dsel, sh_krem;
    __shared__ float    xmax_sm[7];
    __shared__ int      tcnt, pcnt;
    __shared__ int      plist[NT];       // tids whose max clears the band

    const int tid = threadIdx.x;
    const int bc  = blockIdx.x;
    const int ch  = bc % C;
    const float* gx = x   + (size_t)bc * (HW * HW);
    float*       go = out + (size_t)bc * (HW * HW);

    if (tid < 9)  wsm[tid] = wgt[ch * 9 + tid];
    if (tid == 9) wsm[9]   = bias[ch];
    if (tid == 10) tcnt = 0;
    if (tid == 11) pcnt = 0;
    u.hist[0][tid] = 0;
    if (tid < 32) u.hist[0][tid + NT] = 0;

    // ---- zero borders: rows 0 & 57 (full), cols 3 & 60 (rows 1..56) ----
    for (int i = tid; i < 248; i += NT) {
        if      (i < 68)  tile[i] = 0.f;
        else if (i < 136) tile[57 * TS + (i - 68)] = 0.f;
        else if (i < 192) tile[(i - 135) * TS + 3] = 0.f;
        else              tile[(i - 191) * TS + 60] = 0.f;
    }

    // ---- load interior + ZERO-FILL out, division-free strided walk.
    //      (out is 99% zeros; winners are scatter-written in Phase C, which is
    //      ordered after these STGs by the intervening __syncthreads.) ----
    const int r0 = tid / 14;
    const int q4 = tid - r0 * 14;        // float4 index in row, col = 4*q4
    float maxv = 0.0f;
    {
        const float4 z4 = make_float4(0.f, 0.f, 0.f, 0.f);
        const float4* gp = reinterpret_cast<const float4*>(gx) + (r0 * 14 + q4);
        float4*       op = reinterpret_cast<float4*>(go)       + (r0 * 14 + q4);
        float*        tp = &tile[(r0 + 1) * TS + q4 * 4 + 4];
        #pragma unroll
        for (int it = 0; it < 4; ++it) {
            if (it < 3 || r0 < 8) {
                float4 v = *gp;
                maxv = fmaxf(maxv, fmaxf(fmaxf(fabsf(v.x), fabsf(v.y)),
                                         fmaxf(fabsf(v.z), fabsf(v.w))));
                *reinterpret_cast<float4*>(tp) = v;
                *op = z4;
            }
            gp += 16 * 14;
            op += 16 * 14;
            tp += 16 * TS;
        }
    }
    #pragma unroll
    for (int d = 16; d > 0; d >>= 1)
        maxv = fmaxf(maxv, __shfl_xor_sync(0xFFFFFFFFu, maxv, d));
    if ((tid & 31) == 0) xmax_sm[tid >> 5] = maxv;
    __syncthreads();

    const float w0 = wsm[0], w1 = wsm[1], w2 = wsm[2];
    const float w3 = wsm[3], w4 = wsm[4], w5 = wsm[5];
    const float w6 = wsm[6], w7 = wsm[7], w8 = wsm[8];
    const float bv = wsm[9];

    const int row0 = (tid >> 3) * 2;      // 0,2,...,54
    const int c0   = (tid & 7) * NV;      // 0,7,...,49
    const int lane = tid & 31;

    // ---- conv pass 1: 2x7 patch, rolling window; track ONLY the max ----
    float smax = -3.4e38f;
    {
        const float* R0 = &tile[row0 * TS + c0 + 3];
        const float* R1 = R0 + TS;
        const float* R2 = R1 + TS;
        const float* R3 = R2 + TS;
        float a00 = R0[0], a01 = R0[1];
        float a10 = R1[0], a11 = R1[1];
        float a20 = R2[0], a21 = R2[1];
        float a30 = R3[0], a31 = R3[1];
        #pragma unroll
        for (int j = 0; j < NV; ++j) {
            float a02 = R0[j + 2], a12 = R1[j + 2];
            float a22 = R2[j + 2], a32 = R3[j + 2];
            float s0 = bv;
            s0 = fmaf(w0, a00, s0); s0 = fmaf(w1, a01, s0); s0 = fmaf(w2, a02, s0);
            s0 = fmaf(w3, a10, s0); s0 = fmaf(w4, a11, s0); s0 = fmaf(w5, a12, s0);
            s0 = fmaf(w6, a20, s0); s0 = fmaf(w7, a21, s0); s0 = fmaf(w8, a22, s0);
            float s1 = bv;
            s1 = fmaf(w0, a10, s1); s1 = fmaf(w1, a11, s1); s1 = fmaf(w2, a12, s1);
            s1 = fmaf(w3, a20, s1); s1 = fmaf(w4, a21, s1); s1 = fmaf(w5, a22, s1);
            s1 = fmaf(w6, a30, s1); s1 = fmaf(w7, a31, s1); s1 = fmaf(w8, a32, s1);
            smax = fmaxf(smax, fmaxf(s0, s1));
            a00 = a01; a01 = a02; a10 = a11; a11 = a12;
            a20 = a21; a21 = a22; a30 = a31; a31 = a32;
        }
    }
    unsigned mu = __float_as_uint(smax);
    const unsigned maxkey = mu ^ ((unsigned)(((int)mu) >> 31) | 0x80000000u);

    // ---- 3-pass radix: 24-bit prefix of the rank-KSEL maximum.
    //      trunc24(M30) <= M30, so the band below stays a top-KSEL superset. ----
    unsigned prefix = 0;
    unsigned krem   = KSEL;
    #pragma unroll
    for (int pass = 0; pass < 3; ++pass) {
        const int cur   = pass & 1;
        const int shift = 24 - 8 * pass;
        {
            unsigned v  = maxkey;
            bool ok = (((unsigned long long)v) >> (shift + 8)) ==
                      (unsigned long long)prefix;
            unsigned digit = ok ? ((v >> shift) & 255u) : 0xFFFFFFFFu;
            unsigned m = __match_any_sync(0xFFFFFFFFu, digit);
            if (ok && ((__ffs(m) - 1) == lane))
                atomicAdd(&u.hist[cur][digit], (unsigned)__popc(m));
            if (pass < 2) {                       // pre-zero next buffer
                u.hist[cur ^ 1][tid] = 0;
                if (tid < 32) u.hist[cur ^ 1][tid + NT] = 0;
            }
        }
        __syncthreads();

        if (tid < 32) {
            unsigned loc[8];
            unsigned run = 0;
            #pragma unroll
            for (int j = 7; j >= 0; --j) { run += u.hist[cur][lane * 8 + j]; loc[j] = run; }
            unsigned laneTotal = run;
            unsigned incl = laneTotal;
            #pragma unroll
            for (int d = 1; d < 32; d <<= 1) {
                unsigned t = __shfl_down_sync(0xFFFFFFFFu, incl, d);
                if (lane + d < 32) incl += t;
            }
            unsigned hiSum = incl - laneTotal;
            #pragma unroll
            for (int j = 0; j < 8; ++j) {
                unsigned suf  = hiSum + loc[j];
                unsigned sufn = (j < 7) ? (hiSum + loc[j + 1]) : hiSum;
                if (suf >= krem && sufn < krem) {
                    sh_dsel = (unsigned)(lane * 8 + j);
                    sh_krem = krem - sufn;
                }
            }
        }
        __syncthreads();
        prefix = (prefix << 8) | sh_dsel;
        krem   = sh_krem;
    }
    const unsigned MtruncKey = prefix << 8;     // lower bound of M30's key block

    // ---- guard band: Tc = float(trunc24) - 2E ----
    float xmax = xmax_sm[0];
    #pragma unroll
    for (int i = 1; i < 7; ++i) xmax = fmaxf(xmax, xmax_sm[i]);
    const float wsum = fabsf(w0) + fabsf(w1) + fabsf(w2) + fabsf(w3) + fabsf(w4)
                     + fabsf(w5) + fabsf(w6) + fabsf(w7) + fabsf(w8);
    const float E = (wsum * xmax + fabsf(bv)) * 1.2e-6f;

    unsigned tu = (MtruncKey & 0x80000000u) ? (MtruncKey ^ 0x80000000u) : ~MtruncKey;
    const float Tc = __uint_as_float(tu) - 2.0f * E;

    // ---- Phase A0: passing threads publish tid (one atomic each) ----
    if (smax >= Tc) {
        int qq = atomicAdd(&pcnt, 1);
        plist[qq] = tid;                   // qq < 224 always
    }
    __syncthreads();
    const int np = pcnt;

    // ---- Phase A1 (+fused B): cooperative rescore of flagged pixels; on a hit,
    //      the 9 taps are in registers -> compute the EXACT double score now. ----
    for (int idx = tid; idx < np * 14; idx += NT) {
        int qq    = idx / 14;
        int k     = idx - qq * 14;
        int owner = plist[qq];
        int pr    = ((owner >> 3) * 2) + (k >= NV ? 1 : 0);
        int pc    = ((owner & 7) * NV) + (k >= NV ? k - NV : k);
        const float* t0 = &tile[pr * TS + pc + 3];
        float v0 = t0[0],      v1 = t0[1],      v2 = t0[2];
        float v3 = t0[TS],     v4 = t0[TS + 1], v5 = t0[TS + 2];
        float v6 = t0[2*TS],   v7 = t0[2*TS+1], v8 = t0[2*TS+2];
        float s = bv;
        s = fmaf(w0, v0, s); s = fmaf(w1, v1, s); s = fmaf(w2, v2, s);
        s = fmaf(w3, v3, s); s = fmaf(w4, v4, s); s = fmaf(w5, v5, s);
        s = fmaf(w6, v6, s); s = fmaf(w7, v7, s); s = fmaf(w8, v8, s);
        if (s >= Tc) {
            double d = (double)bv;
            d = fma((double)w0, (double)v0, d);
            d = fma((double)w1, (double)v1, d);
            d = fma((double)w2, (double)v2, d);
            d = fma((double)w3, (double)v3, d);
            d = fma((double)w4, (double)v4, d);
            d = fma((double)w5, (double)v5, d);
            d = fma((double)w6, (double)v6, d);
            d = fma((double)w7, (double)v7, d);
            d = fma((double)w8, (double)v8, d);
            int pos = atomicAdd(&tcnt, 1);
            if (pos < TMAX) { u.cand.csc[pos] = d; u.cand.cidx[pos] = pr * HW + pc; }
        }
    }
    __syncthreads();
    const int ntie = (tcnt < TMAX) ? tcnt : TMAX;

    // ---- Phase C: rank by (double desc, index asc); winners scatter x directly
    //      into the pre-zeroed output (ordered after zero STGs by barriers) ----
    if (tid < ntie) {
        double mys = u.cand.csc[tid];
        int   cpos = u.cand.cidx[tid];
        unsigned rnk = 0;
        for (int qq = 0; qq < ntie; ++qq) {
            double v = u.cand.csc[qq];
            rnk += (v > mys) || (v == mys && u.cand.cidx[qq] < cpos);
        }
        if (rnk < KSEL) {
            int r = cpos / HW, cc = cpos - r * HW;
            go[cpos] = tile[(r + 1) * TS + cc + 4];
        }
    }
}

extern "C" void kernel_launch(void* const* d_in, const int* in_sizes, int n_in,
                              void* d_out, int out_size)
{
    const float* x  = (const float*)d_in[0];
    const float* w  = (const float*)d_in[1];
    const float* b  = (const float*)d_in[2];
    float*       o  = (float*)d_out;
    int C    = in_sizes[2];               // 384
    int n_bc = in_sizes[0] / (HW * HW);   // 12288
    topk_spatial_kernel<<<n_bc, NT>>>(x, w, b, o, C);
}